// round 1
// baseline (speedup 1.0000x reference)
#include <cuda_runtime.h>
#include <cuda_bf16.h>

#define N_NODES 100000
#define N_EDGES 1600000
#define D_IN 128
#define D_HID 256
#define D_OUT 128

// Scratch (device globals; no runtime allocation allowed)
__device__ __align__(16) float g_AX[(size_t)N_NODES * D_IN];   // 51.2 MB
__device__ __align__(16) float g_H[(size_t)N_NODES * D_HID];   // 102.4 MB

// ---------------------------------------------------------------------------
// Kernel 1: AX = (1 + eps) * x   (also serves as accumulator init)
// ---------------------------------------------------------------------------
__global__ void init_ax_kernel(const float* __restrict__ x,
                               const float* __restrict__ eps) {
    int i = blockIdx.x * blockDim.x + threadIdx.x;
    const int total4 = N_NODES * D_IN / 4;
    if (i >= total4) return;
    float s = 1.0f + eps[0];
    float4 v = reinterpret_cast<const float4*>(x)[i];
    v.x *= s; v.y *= s; v.z *= s; v.w *= s;
    reinterpret_cast<float4*>(g_AX)[i] = v;
}

// ---------------------------------------------------------------------------
// Kernel 2: edge scatter — one warp per edge, red.global.add.v4.f32
// ---------------------------------------------------------------------------
__global__ void scatter_kernel(const float* __restrict__ x,
                               const float* __restrict__ edge_vals,
                               const int* __restrict__ edge_src,
                               const int* __restrict__ edge_dst) {
    long long tid = (long long)blockIdx.x * blockDim.x + threadIdx.x;
    int e = (int)(tid >> 5);
    int lane = (int)(tid & 31);
    if (e >= N_EDGES) return;

    float v = edge_vals[e];
    int s = edge_src[e];
    int d = edge_dst[e];

    const float4* xrow = reinterpret_cast<const float4*>(x + (size_t)s * D_IN);
    float4 xv = xrow[lane];
    float4 r = make_float4(xv.x * v, xv.y * v, xv.z * v, xv.w * v);

    float* addr = g_AX + (size_t)d * D_IN + lane * 4;
    asm volatile("red.global.add.v4.f32 [%0], {%1, %2, %3, %4};"
                 :: "l"(addr), "f"(r.x), "f"(r.y), "f"(r.z), "f"(r.w)
                 : "memory");
}

// ---------------------------------------------------------------------------
// Kernel 3: tiled SIMT fp32 GEMM with fused bias (+ optional ReLU)
//   C[M,N] = A[M,K] @ B[K,N] + bias;  row-major everywhere.
//   BM=64, BN=64, BK=32, 256 threads, each thread computes 4x4.
//   N and K are multiples of (BN, BK); only M is ragged.
// ---------------------------------------------------------------------------
template <bool RELU>
__global__ void gemm_bias_kernel(const float* __restrict__ A,
                                 const float* __restrict__ B,
                                 const float* __restrict__ bias,
                                 float* __restrict__ C,
                                 int M, int N, int K) {
    constexpr int BM = 64, BN = 64, BK = 32, TM = 4, TN = 4;

    __shared__ float As[BK][BM];   // transposed A tile
    __shared__ float Bs[BK][BN];

    const int tid = threadIdx.x;           // 0..255
    const int mBase = blockIdx.y * BM;
    const int nBase = blockIdx.x * BN;

    // A-load mapping: float4 along K. 8 float4 per row-chunk; 32 rows/pass, 2 passes.
    const int aRow = tid / (BK / 4);       // 0..31
    const int aCol = tid % (BK / 4);       // 0..7 (float4 index)
    // B-load mapping: float4 along N. 16 float4 per row; 16 rows/pass, 2 passes.
    const int bRow = tid / (BN / 4);       // 0..15
    const int bCol = tid % (BN / 4);       // 0..15

    const int threadRow = tid / (BN / TN); // 0..15
    const int threadCol = tid % (BN / TN); // 0..15

    float acc[TM][TN];
#pragma unroll
    for (int i = 0; i < TM; i++)
#pragma unroll
        for (int j = 0; j < TN; j++) acc[i][j] = 0.0f;

    for (int k0 = 0; k0 < K; k0 += BK) {
        // Load A tile (guard ragged M rows with zeros), store transposed.
#pragma unroll
        for (int it = 0; it < 2; it++) {
            int row = aRow + it * 32;              // 0..63 within tile
            int gRow = mBase + row;
            float4 av;
            if (gRow < M) {
                av = reinterpret_cast<const float4*>(
                        A + (size_t)gRow * K + k0)[aCol];
            } else {
                av = make_float4(0.f, 0.f, 0.f, 0.f);
            }
            As[aCol * 4 + 0][row] = av.x;
            As[aCol * 4 + 1][row] = av.y;
            As[aCol * 4 + 2][row] = av.z;
            As[aCol * 4 + 3][row] = av.w;
        }
        // Load B tile.
#pragma unroll
        for (int it = 0; it < 2; it++) {
            int row = bRow + it * 16;              // 0..31 within tile
            float4 bv = reinterpret_cast<const float4*>(
                    B + (size_t)(k0 + row) * N + nBase)[bCol];
            reinterpret_cast<float4*>(&Bs[row][0])[bCol] = bv;
        }
        __syncthreads();

#pragma unroll
        for (int k = 0; k < BK; k++) {
            float rm[TM], rn[TN];
#pragma unroll
            for (int i = 0; i < TM; i++) rm[i] = As[k][threadRow * TM + i];
#pragma unroll
            for (int j = 0; j < TN; j++) rn[j] = Bs[k][threadCol * TN + j];
#pragma unroll
            for (int i = 0; i < TM; i++)
#pragma unroll
                for (int j = 0; j < TN; j++)
                    acc[i][j] = fmaf(rm[i], rn[j], acc[i][j]);
        }
        __syncthreads();
    }

    // Epilogue: bias (+ReLU), guarded store.
#pragma unroll
    for (int i = 0; i < TM; i++) {
        int gRow = mBase + threadRow * TM + i;
        if (gRow >= M) continue;
        float* crow = C + (size_t)gRow * N + nBase + threadCol * TN;
        float4 out;
        float b0 = bias[nBase + threadCol * TN + 0];
        float b1 = bias[nBase + threadCol * TN + 1];
        float b2 = bias[nBase + threadCol * TN + 2];
        float b3 = bias[nBase + threadCol * TN + 3];
        out.x = acc[i][0] + b0;
        out.y = acc[i][1] + b1;
        out.z = acc[i][2] + b2;
        out.w = acc[i][3] + b3;
        if (RELU) {
            out.x = fmaxf(out.x, 0.f);
            out.y = fmaxf(out.y, 0.f);
            out.z = fmaxf(out.z, 0.f);
            out.w = fmaxf(out.w, 0.f);
        }
        reinterpret_cast<float4*>(crow)[0] = out;
    }
}

// ---------------------------------------------------------------------------
// Launch
// ---------------------------------------------------------------------------
extern "C" void kernel_launch(void* const* d_in, const int* in_sizes, int n_in,
                              void* d_out, int out_size) {
    const float* x         = (const float*)d_in[0];
    const float* edge_vals = (const float*)d_in[1];
    const float* W1        = (const float*)d_in[2];
    const float* b1        = (const float*)d_in[3];
    const float* W2        = (const float*)d_in[4];
    const float* b2        = (const float*)d_in[5];
    const float* eps       = (const float*)d_in[6];
    const int*   edge_src  = (const int*)d_in[7];
    const int*   edge_dst  = (const int*)d_in[8];
    float* out = (float*)d_out;

    float* g_ax_ptr;
    float* g_h_ptr;
    cudaGetSymbolAddress((void**)&g_ax_ptr, g_AX);
    cudaGetSymbolAddress((void**)&g_h_ptr, g_H);

    // 1) AX = (1+eps)*x
    {
        int total4 = N_NODES * D_IN / 4;
        int threads = 256;
        int blocks = (total4 + threads - 1) / threads;
        init_ax_kernel<<<blocks, threads>>>(x, eps);
    }
    // 2) scatter edges
    {
        long long totalThreads = (long long)N_EDGES * 32;
        int threads = 256;
        long long blocks = (totalThreads + threads - 1) / threads;
        scatter_kernel<<<(unsigned)blocks, threads>>>(x, edge_vals, edge_src, edge_dst);
    }
    // 3) H = relu(AX @ W1 + b1)
    {
        dim3 grid(D_HID / 64, (N_NODES + 63) / 64);
        gemm_bias_kernel<true><<<grid, 256>>>(g_ax_ptr, W1, b1, g_h_ptr,
                                              N_NODES, D_HID, D_IN);
    }
    // 4) out = H @ W2 + b2
    {
        dim3 grid(D_OUT / 64, (N_NODES + 63) / 64);
        gemm_bias_kernel<false><<<grid, 256>>>(g_h_ptr, W2, b2, out,
                                               N_NODES, D_OUT, D_HID);
    }
}

// round 2
// speedup vs baseline: 1.0399x; 1.0399x over previous
#include <cuda_runtime.h>
#include <cuda_bf16.h>

#define N_NODES 100000
#define N_EDGES 1600000
#define D_IN 128
#define D_HID 256
#define D_OUT 128

// Scratch (device globals; no runtime allocation allowed)
__device__ __align__(16) float g_AX[(size_t)N_NODES * D_IN];   // 51.2 MB
__device__ __align__(16) float g_H[(size_t)N_NODES * D_HID];   // 102.4 MB

// ---------------------------------------------------------------------------
// Kernel 1: AX = (1 + eps) * x   (also serves as accumulator init)
// ---------------------------------------------------------------------------
__global__ void init_ax_kernel(const float* __restrict__ x,
                               const float* __restrict__ eps) {
    int i = blockIdx.x * blockDim.x + threadIdx.x;
    const int total4 = N_NODES * D_IN / 4;
    if (i >= total4) return;
    float s = 1.0f + eps[0];
    float4 v = reinterpret_cast<const float4*>(x)[i];
    v.x *= s; v.y *= s; v.z *= s; v.w *= s;
    reinterpret_cast<float4*>(g_AX)[i] = v;
}

// ---------------------------------------------------------------------------
// Kernel 2: edge scatter — one warp per edge, red.global.add.v4.f32
// ---------------------------------------------------------------------------
__global__ void scatter_kernel(const float* __restrict__ x,
                               const float* __restrict__ edge_vals,
                               const int* __restrict__ edge_src,
                               const int* __restrict__ edge_dst) {
    long long tid = (long long)blockIdx.x * blockDim.x + threadIdx.x;
    int e = (int)(tid >> 5);
    int lane = (int)(tid & 31);
    if (e >= N_EDGES) return;

    float v = edge_vals[e];
    int s = edge_src[e];
    int d = edge_dst[e];

    const float4* xrow = reinterpret_cast<const float4*>(x + (size_t)s * D_IN);
    float4 xv = xrow[lane];
    float4 r = make_float4(xv.x * v, xv.y * v, xv.z * v, xv.w * v);

    float* addr = g_AX + (size_t)d * D_IN + lane * 4;
    asm volatile("red.global.add.v4.f32 [%0], {%1, %2, %3, %4};"
                 :: "l"(addr), "f"(r.x), "f"(r.y), "f"(r.z), "f"(r.w)
                 : "memory");
}

// ---------------------------------------------------------------------------
// Kernel 3: 128x128x16 double-buffered SIMT fp32 GEMM, fused bias (+ReLU).
//   C[M,N] = A[M,K] @ B[K,N] + bias; row-major. 256 threads, 8x8 per thread.
//   N % 128 == 0, K % 16 == 0; M ragged (guarded).
// ---------------------------------------------------------------------------
template <bool RELU>
__global__ void __launch_bounds__(256, 2)
gemm128_kernel(const float* __restrict__ A,
               const float* __restrict__ B,
               const float* __restrict__ bias,
               float* __restrict__ C,
               int M, int N, int K) {
    constexpr int BM = 128, BN = 128, BK = 16, TM = 8, TN = 8;

    __shared__ float As[2][BK][BM];   // transposed A tile
    __shared__ float Bs[2][BK][BN];

    const int tid = threadIdx.x;            // 0..255
    const int mBase = blockIdx.y * BM;
    const int nBase = blockIdx.x * BN;

    const int aRow = tid >> 2;               // 0..63
    const int aCol = tid & 3;                // 0..3 (float4 along K)
    const int bRow = tid >> 5;               // 0..7
    const int bCol = tid & 31;               // 0..31 (float4 along N)

    const int tRow = tid >> 4;               // 0..15
    const int tCol = tid & 15;               // 0..15

    float acc[TM][TN];
#pragma unroll
    for (int i = 0; i < TM; i++)
#pragma unroll
        for (int j = 0; j < TN; j++) acc[i][j] = 0.0f;

    float4 aReg[2], bReg[2];

    // --- global tile load into registers ---
#define LOAD_G(k0)                                                            \
    {                                                                         \
        _Pragma("unroll")                                                     \
        for (int it = 0; it < 2; it++) {                                      \
            int row = aRow + it * 64;                                         \
            int gRow = mBase + row;                                           \
            if (gRow < M)                                                     \
                aReg[it] = *reinterpret_cast<const float4*>(                  \
                    A + (size_t)gRow * K + (k0) + aCol * 4);                  \
            else                                                              \
                aReg[it] = make_float4(0.f, 0.f, 0.f, 0.f);                   \
        }                                                                     \
        _Pragma("unroll")                                                     \
        for (int it = 0; it < 2; it++) {                                      \
            int row = bRow + it * 8;                                          \
            bReg[it] = *reinterpret_cast<const float4*>(                      \
                B + (size_t)((k0) + row) * N + nBase + bCol * 4);             \
        }                                                                     \
    }

    // --- registers -> smem buffer ---
#define STORE_S(buf)                                                          \
    {                                                                         \
        _Pragma("unroll")                                                     \
        for (int it = 0; it < 2; it++) {                                      \
            int row = aRow + it * 64;                                         \
            As[buf][aCol * 4 + 0][row] = aReg[it].x;                          \
            As[buf][aCol * 4 + 1][row] = aReg[it].y;                          \
            As[buf][aCol * 4 + 2][row] = aReg[it].z;                          \
            As[buf][aCol * 4 + 3][row] = aReg[it].w;                          \
            *reinterpret_cast<float4*>(&Bs[buf][bRow + it * 8][bCol * 4]) =   \
                bReg[it];                                                     \
        }                                                                     \
    }

    LOAD_G(0);
    STORE_S(0);
    __syncthreads();

    const int T = K / BK;
    for (int t = 0; t < T; t++) {
        const int buf = t & 1;
        if (t + 1 < T) LOAD_G((t + 1) * BK);

#pragma unroll
        for (int k = 0; k < BK; k++) {
            float rm[TM], rn[TN];
            *reinterpret_cast<float4*>(&rm[0]) =
                *reinterpret_cast<const float4*>(&As[buf][k][tRow * TM]);
            *reinterpret_cast<float4*>(&rm[4]) =
                *reinterpret_cast<const float4*>(&As[buf][k][tRow * TM + 4]);
            *reinterpret_cast<float4*>(&rn[0]) =
                *reinterpret_cast<const float4*>(&Bs[buf][k][tCol * TN]);
            *reinterpret_cast<float4*>(&rn[4]) =
                *reinterpret_cast<const float4*>(&Bs[buf][k][tCol * TN + 4]);
#pragma unroll
            for (int i = 0; i < TM; i++)
#pragma unroll
                for (int j = 0; j < TN; j++)
                    acc[i][j] = fmaf(rm[i], rn[j], acc[i][j]);
        }

        if (t + 1 < T) {
            STORE_S(buf ^ 1);
            __syncthreads();
        }
    }

    // Epilogue: bias (+ReLU), guarded float4 stores.
    float4 bv0 = *reinterpret_cast<const float4*>(bias + nBase + tCol * TN);
    float4 bv1 = *reinterpret_cast<const float4*>(bias + nBase + tCol * TN + 4);
#pragma unroll
    for (int i = 0; i < TM; i++) {
        int gRow = mBase + tRow * TM + i;
        if (gRow >= M) continue;
        float* crow = C + (size_t)gRow * N + nBase + tCol * TN;
        float4 o0, o1;
        o0.x = acc[i][0] + bv0.x;  o0.y = acc[i][1] + bv0.y;
        o0.z = acc[i][2] + bv0.z;  o0.w = acc[i][3] + bv0.w;
        o1.x = acc[i][4] + bv1.x;  o1.y = acc[i][5] + bv1.y;
        o1.z = acc[i][6] + bv1.z;  o1.w = acc[i][7] + bv1.w;
        if (RELU) {
            o0.x = fmaxf(o0.x, 0.f); o0.y = fmaxf(o0.y, 0.f);
            o0.z = fmaxf(o0.z, 0.f); o0.w = fmaxf(o0.w, 0.f);
            o1.x = fmaxf(o1.x, 0.f); o1.y = fmaxf(o1.y, 0.f);
            o1.z = fmaxf(o1.z, 0.f); o1.w = fmaxf(o1.w, 0.f);
        }
        reinterpret_cast<float4*>(crow)[0] = o0;
        reinterpret_cast<float4*>(crow)[1] = o1;
    }
#undef LOAD_G
#undef STORE_S
}

// ---------------------------------------------------------------------------
// Launch
// ---------------------------------------------------------------------------
extern "C" void kernel_launch(void* const* d_in, const int* in_sizes, int n_in,
                              void* d_out, int out_size) {
    const float* x         = (const float*)d_in[0];
    const float* edge_vals = (const float*)d_in[1];
    const float* W1        = (const float*)d_in[2];
    const float* b1        = (const float*)d_in[3];
    const float* W2        = (const float*)d_in[4];
    const float* b2        = (const float*)d_in[5];
    const float* eps       = (const float*)d_in[6];
    const int*   edge_src  = (const int*)d_in[7];
    const int*   edge_dst  = (const int*)d_in[8];
    float* out = (float*)d_out;

    float* g_ax_ptr;
    float* g_h_ptr;
    cudaGetSymbolAddress((void**)&g_ax_ptr, g_AX);
    cudaGetSymbolAddress((void**)&g_h_ptr, g_H);

    // 1) AX = (1+eps)*x
    {
        int total4 = N_NODES * D_IN / 4;
        int threads = 256;
        int blocks = (total4 + threads - 1) / threads;
        init_ax_kernel<<<blocks, threads>>>(x, eps);
    }
    // 2) scatter edges
    {
        long long totalThreads = (long long)N_EDGES * 32;
        int threads = 256;
        long long blocks = (totalThreads + threads - 1) / threads;
        scatter_kernel<<<(unsigned)blocks, threads>>>(x, edge_vals, edge_src, edge_dst);
    }
    // 3) H = relu(AX @ W1 + b1)
    {
        dim3 grid(D_HID / 128, (N_NODES + 127) / 128);
        gemm128_kernel<true><<<grid, 256>>>(g_ax_ptr, W1, b1, g_h_ptr,
                                            N_NODES, D_HID, D_IN);
    }
    // 4) out = H @ W2 + b2
    {
        dim3 grid(D_OUT / 128, (N_NODES + 127) / 128);
        gemm128_kernel<false><<<grid, 256>>>(g_h_ptr, W2, b2, out,
                                             N_NODES, D_OUT, D_HID);
    }
}

// round 5
// speedup vs baseline: 1.5370x; 1.4780x over previous
#include <cuda_runtime.h>
#include <cuda_bf16.h>
#include <cstdint>

#define N_NODES 100000
#define N_EDGES 1600000
#define D_IN 128
#define D_HID 256
#define D_OUT 128

// Scratch (device globals; no runtime allocation allowed)
__device__ __align__(16) float g_AX[(size_t)N_NODES * D_IN];   // 51.2 MB
__device__ __align__(16) float g_H[(size_t)N_NODES * D_HID];   // 102.4 MB

// ---------------------------------------------------------------------------
// Kernel 1: AX = (1 + eps) * x   (accumulator init)
// ---------------------------------------------------------------------------
__global__ void init_ax_kernel(const float* __restrict__ x,
                               const float* __restrict__ eps) {
    int i = blockIdx.x * blockDim.x + threadIdx.x;
    const int total4 = N_NODES * D_IN / 4;
    if (i >= total4) return;
    float s = 1.0f + eps[0];
    float4 v = reinterpret_cast<const float4*>(x)[i];
    v.x *= s; v.y *= s; v.z *= s; v.w *= s;
    reinterpret_cast<float4*>(g_AX)[i] = v;
}

// ---------------------------------------------------------------------------
// Kernel 2: edge scatter — one warp per edge, red.global.add.v4.f32
// ---------------------------------------------------------------------------
__global__ void scatter_kernel(const float* __restrict__ x,
                               const float* __restrict__ edge_vals,
                               const int* __restrict__ edge_src,
                               const int* __restrict__ edge_dst) {
    long long tid = (long long)blockIdx.x * blockDim.x + threadIdx.x;
    int e = (int)(tid >> 5);
    int lane = (int)(tid & 31);
    if (e >= N_EDGES) return;

    float v = edge_vals[e];
    int s = edge_src[e];
    int d = edge_dst[e];

    const float4* xrow = reinterpret_cast<const float4*>(x + (size_t)s * D_IN);
    float4 xv = xrow[lane];
    float4 r = make_float4(xv.x * v, xv.y * v, xv.z * v, xv.w * v);

    float* addr = g_AX + (size_t)d * D_IN + lane * 4;
    asm volatile("red.global.add.v4.f32 [%0], {%1, %2, %3, %4};"
                 :: "l"(addr), "f"(r.x), "f"(r.y), "f"(r.z), "f"(r.w)
                 : "memory");
}

// ---------------------------------------------------------------------------
// Kernel 3: 3x-bf16-split tensor-core GEMM, static 48KB smem, single buffer.
//   C = A @ B + bias (optional ReLU). A[M,K], B[K,N], C[M,N] row-major fp32.
//   Split a = a_hi + a_lo (bf16); C ≈ Ahi*Bhi + Ahi*Blo + Alo*Bhi.
//   CTA tile 128x64x64, 8 warps (2m x 4n), warp tile 64x16.
//   XOR-swizzled 128B smem rows, conflict-free ldmatrix.
// ---------------------------------------------------------------------------

#define LDSM_X4(R0, R1, R2, R3, ADDR)                                         \
    asm volatile("ldmatrix.sync.aligned.m8n8.x4.shared.b16 {%0,%1,%2,%3}, [%4];" \
                 : "=r"(R0), "=r"(R1), "=r"(R2), "=r"(R3) : "r"(ADDR))

#define LDSM_X4_T(R0, R1, R2, R3, ADDR)                                       \
    asm volatile("ldmatrix.sync.aligned.m8n8.x4.trans.shared.b16 {%0,%1,%2,%3}, [%4];" \
                 : "=r"(R0), "=r"(R1), "=r"(R2), "=r"(R3) : "r"(ADDR))

#define MMA16816(D, A, B0, B1)                                                \
    asm volatile("mma.sync.aligned.m16n8k16.row.col.f32.bf16.bf16.f32 "       \
                 "{%0,%1,%2,%3}, {%4,%5,%6,%7}, {%8,%9}, {%0,%1,%2,%3};"      \
                 : "+f"(D[0]), "+f"(D[1]), "+f"(D[2]), "+f"(D[3])             \
                 : "r"(A[0]), "r"(A[1]), "r"(A[2]), "r"(A[3]),                \
                   "r"(B0), "r"(B1))

__device__ __forceinline__ uint32_t pack_bf16(__nv_bfloat16 a, __nv_bfloat16 b) {
    __nv_bfloat162 t;
    t.x = a; t.y = b;
    return *reinterpret_cast<uint32_t*>(&t);
}

__device__ __forceinline__ void cvt_hilo(float4 v, uint2& hi, uint2& lo) {
    __nv_bfloat16 hx = __float2bfloat16_rn(v.x);
    __nv_bfloat16 hy = __float2bfloat16_rn(v.y);
    __nv_bfloat16 hz = __float2bfloat16_rn(v.z);
    __nv_bfloat16 hw = __float2bfloat16_rn(v.w);
    float rx = v.x - __bfloat162float(hx);
    float ry = v.y - __bfloat162float(hy);
    float rz = v.z - __bfloat162float(hz);
    float rw = v.w - __bfloat162float(hw);
    hi.x = pack_bf16(hx, hy);
    hi.y = pack_bf16(hz, hw);
    lo.x = pack_bf16(__float2bfloat16_rn(rx), __float2bfloat16_rn(ry));
    lo.y = pack_bf16(__float2bfloat16_rn(rz), __float2bfloat16_rn(rw));
}

// Static smem layout (bytes):
//   AsHi [128 rows x 128B] @ 0      | AsLo @ 16384
//   BsHi [ 64 rows x 128B] @ 32768  | BsLo @ 40960     (total 49152 = 48KB)
#define AS_LO_OFF 16384
#define BS_HI_OFF 32768
#define BS_LO_OFF 40960

template <bool RELU>
__global__ void __launch_bounds__(256)
gemm_bf16x3_kernel(const float* __restrict__ A,
                   const float* __restrict__ B,
                   const float* __restrict__ bias,
                   float* __restrict__ C,
                   int M, int N, int K) {
    __shared__ __align__(16) char smem[49152];
    const uint32_t sbase = (uint32_t)__cvta_generic_to_shared(smem);

    const int tid = threadIdx.x;
    const int lane = tid & 31;
    const int warp = tid >> 5;
    const int wm = (warp >> 2) * 64;     // warp m offset: 0 or 64
    const int wn = (warp & 3) * 16;      // warp n offset: 0,16,32,48

    const int mBase = blockIdx.y * 128;
    const int nBase = blockIdx.x * 64;

    // loader indices
    const int ar = tid >> 1;             // A row 0..127 (2 threads/row)
    const int ah = tid & 1;
    const int br = tid >> 2;             // B row 0..63  (4 threads/row)
    const int bl = tid & 3;

    float acc[4][2][4];
#pragma unroll
    for (int mi = 0; mi < 4; mi++)
#pragma unroll
        for (int j = 0; j < 2; j++)
#pragma unroll
            for (int r = 0; r < 4; r++) acc[mi][j][r] = 0.0f;

    float4 aReg[8], bReg[4];

#define LDG_STAGE(k0)                                                          \
    {                                                                          \
        int gRow = mBase + ar;                                                 \
        _Pragma("unroll")                                                      \
        for (int i = 0; i < 8; i++) {                                          \
            int q = i * 2 + ah;  /* float4 idx along K, 0..15 */               \
            aReg[i] = (gRow < M)                                               \
                ? *reinterpret_cast<const float4*>(A + (size_t)gRow * K + (k0) + q * 4) \
                : make_float4(0.f, 0.f, 0.f, 0.f);                             \
        }                                                                      \
        _Pragma("unroll")                                                      \
        for (int i = 0; i < 4; i++) {                                          \
            int q = i * 4 + bl;  /* float4 idx along N, 0..15 */               \
            bReg[i] = *reinterpret_cast<const float4*>(                        \
                B + (size_t)((k0) + br) * N + nBase + q * 4);                  \
        }                                                                      \
    }

#define STS_STAGE()                                                            \
    {                                                                          \
        _Pragma("unroll")                                                      \
        for (int i = 0; i < 8; i++) {                                          \
            int q = i * 2 + ah;                                                \
            int sc = (q >> 1) ^ (ar & 7);                                      \
            uint32_t off = ar * 128 + sc * 16 + (q & 1) * 8;                   \
            uint2 hi, lo;                                                      \
            cvt_hilo(aReg[i], hi, lo);                                         \
            *reinterpret_cast<uint2*>(smem + off) = hi;                        \
            *reinterpret_cast<uint2*>(smem + AS_LO_OFF + off) = lo;            \
        }                                                                      \
        _Pragma("unroll")                                                      \
        for (int i = 0; i < 4; i++) {                                          \
            int q = i * 4 + bl;                                                \
            int sc = (q >> 1) ^ (br & 7);                                      \
            uint32_t off = br * 128 + sc * 16 + (q & 1) * 8;                   \
            uint2 hi, lo;                                                      \
            cvt_hilo(bReg[i], hi, lo);                                         \
            *reinterpret_cast<uint2*>(smem + BS_HI_OFF + off) = hi;            \
            *reinterpret_cast<uint2*>(smem + BS_LO_OFF + off) = lo;            \
        }                                                                      \
    }

    LDG_STAGE(0);
    STS_STAGE();
    __syncthreads();

    const int T = K >> 6;
    for (int t = 0; t < T; t++) {
        if (t + 1 < T) LDG_STAGE((t + 1) << 6);

#pragma unroll
        for (int ks = 0; ks < 4; ks++) {
            uint32_t ahi[4][4], alo[4][4], bhi[2][2], blo[2][2];
            const int g = lane >> 3;
            // A fragments: 4 m16 tiles (hi + lo)
#pragma unroll
            for (int mi = 0; mi < 4; mi++) {
                int r = wm + mi * 16 + ((g & 1) << 3) + (lane & 7);
                int kc = ks * 2 + (g >> 1);           // 16B chunk along K
                int sc = kc ^ (r & 7);
                uint32_t addr = sbase + r * 128 + sc * 16;
                LDSM_X4(ahi[mi][0], ahi[mi][1], ahi[mi][2], ahi[mi][3], addr);
                LDSM_X4(alo[mi][0], alo[mi][1], alo[mi][2], alo[mi][3],
                        addr + AS_LO_OFF);
            }
            // B fragments: one n16 group -> 2 n8 frags (hi + lo)
            {
                int kr = ks * 16 + ((g & 1) << 3) + (lane & 7);
                int noff = wn + ((g >> 1) << 3);
                int sc = (noff >> 3) ^ (kr & 7);
                uint32_t addr = sbase + BS_HI_OFF + kr * 128 + sc * 16;
                LDSM_X4_T(bhi[0][0], bhi[0][1], bhi[1][0], bhi[1][1], addr);
                LDSM_X4_T(blo[0][0], blo[0][1], blo[1][0], blo[1][1],
                          addr + 8192);
            }
            // 3-term MMAs
#pragma unroll
            for (int mi = 0; mi < 4; mi++)
#pragma unroll
                for (int j = 0; j < 2; j++) {
                    MMA16816(acc[mi][j], ahi[mi], bhi[j][0], bhi[j][1]);
                    MMA16816(acc[mi][j], ahi[mi], blo[j][0], blo[j][1]);
                    MMA16816(acc[mi][j], alo[mi], bhi[j][0], bhi[j][1]);
                }
        }

        if (t + 1 < T) {
            __syncthreads();   // compute done before overwrite
            STS_STAGE();
            __syncthreads();
        }
    }

    // Epilogue: bias (+ReLU), float2 stores.
    const int cr = lane >> 2;
    const int cc = (lane & 3) * 2;
    float2 bv[2];
#pragma unroll
    for (int j = 0; j < 2; j++)
        bv[j] = *reinterpret_cast<const float2*>(bias + nBase + wn + j * 8 + cc);

#pragma unroll
    for (int mi = 0; mi < 4; mi++) {
        int row0 = mBase + wm + mi * 16 + cr;
        int row1 = row0 + 8;
#pragma unroll
        for (int j = 0; j < 2; j++) {
            int col = nBase + wn + j * 8 + cc;
            float2 o0, o1;
            o0.x = acc[mi][j][0] + bv[j].x;
            o0.y = acc[mi][j][1] + bv[j].y;
            o1.x = acc[mi][j][2] + bv[j].x;
            o1.y = acc[mi][j][3] + bv[j].y;
            if (RELU) {
                o0.x = fmaxf(o0.x, 0.f); o0.y = fmaxf(o0.y, 0.f);
                o1.x = fmaxf(o1.x, 0.f); o1.y = fmaxf(o1.y, 0.f);
            }
            if (row0 < M)
                *reinterpret_cast<float2*>(C + (size_t)row0 * N + col) = o0;
            if (row1 < M)
                *reinterpret_cast<float2*>(C + (size_t)row1 * N + col) = o1;
        }
    }
#undef LDG_STAGE
#undef STS_STAGE
}

// ---------------------------------------------------------------------------
// Launch
// ---------------------------------------------------------------------------
extern "C" void kernel_launch(void* const* d_in, const int* in_sizes, int n_in,
                              void* d_out, int out_size) {
    const float* x         = (const float*)d_in[0];
    const float* edge_vals = (const float*)d_in[1];
    const float* W1        = (const float*)d_in[2];
    const float* b1        = (const float*)d_in[3];
    const float* W2        = (const float*)d_in[4];
    const float* b2        = (const float*)d_in[5];
    const float* eps       = (const float*)d_in[6];
    const int*   edge_src  = (const int*)d_in[7];
    const int*   edge_dst  = (const int*)d_in[8];
    float* out = (float*)d_out;

    float* g_ax_ptr;
    float* g_h_ptr;
    cudaGetSymbolAddress((void**)&g_ax_ptr, g_AX);
    cudaGetSymbolAddress((void**)&g_h_ptr, g_H);

    // 1) AX = (1+eps)*x
    {
        int total4 = N_NODES * D_IN / 4;
        int threads = 256;
        int blocks = (total4 + threads - 1) / threads;
        init_ax_kernel<<<blocks, threads>>>(x, eps);
    }
    // 2) scatter edges
    {
        long long totalThreads = (long long)N_EDGES * 32;
        int threads = 256;
        long long blocks = (totalThreads + threads - 1) / threads;
        scatter_kernel<<<(unsigned)blocks, threads>>>(x, edge_vals, edge_src, edge_dst);
    }
    // 3) H = relu(AX @ W1 + b1)
    {
        dim3 grid(D_HID / 64, (N_NODES + 127) / 128);
        gemm_bf16x3_kernel<true><<<grid, 256>>>(g_ax_ptr, W1, b1, g_h_ptr,
                                                N_NODES, D_HID, D_IN);
    }
    // 4) out = H @ W2 + b2
    {
        dim3 grid(D_OUT / 64, (N_NODES + 127) / 128);
        gemm_bf16x3_kernel<false><<<grid, 256>>>(g_h_ptr, W2, b2, out,
                                                 N_NODES, D_OUT, D_HID);
    }
}